// round 15
// baseline (speedup 1.0000x reference)
#include <cuda_runtime.h>
#include <cuda_fp16.h>
#include <cstdint>

#define T_STEPS 30
#define NT 512
#define PITCH 336                 // A row pitch bytes (ldmatrix conflict-free)

// smem byte offsets
#define A_OFF    0                // 64 x 336 = 21504
#define BIAS_OFF 21504            // 512 f32
#define WOUT_OFF 23552            // 256 f32
#define WSP_OFF  24576            // 32 f32
#define BSP_OFF  24704            // 16 f32
#define BOUT_OFF 24768            // 2 f32
#define FLAG_OFF 24784            // skew flag
#define RELP_OFF 24800            // + g*2048 ; 8nc x 32row x 2 f32
#define RELS_OFF 28896            // + g*256  ; 32row x 2 f32
#define SMEM_REQ (29408 + 128)

// B image: 9 chunks x [ntg(64)][lane(32)][bh0,bh1,bl0,bl1] (fragment-packed, L2-resident)
__device__ uint32_t g_B[9 * 8192];
__device__ float    g_bias[512];   // indexed by n = 4u+g

__device__ __forceinline__ uint32_t smem_u32(const void* p) {
    uint32_t a;
    asm("{ .reg .u64 t; cvta.to.shared.u64 t, %1; cvt.u32.u64 %0, t; }" : "=r"(a) : "l"(p));
    return a;
}
__device__ __forceinline__ void mma16816(float* d, const uint32_t* a, uint32_t b0, uint32_t b1) {
    asm volatile("mma.sync.aligned.m16n8k16.row.col.f32.f16.f16.f32 "
                 "{%0,%1,%2,%3}, {%4,%5,%6,%7}, {%8,%9}, {%0,%1,%2,%3};"
                 : "+f"(d[0]), "+f"(d[1]), "+f"(d[2]), "+f"(d[3])
                 : "r"(a[0]), "r"(a[1]), "r"(a[2]), "r"(a[3]), "r"(b0), "r"(b1));
}
__device__ __forceinline__ void ldmatrix4(uint32_t* a, uint32_t addr) {
    asm volatile("ldmatrix.sync.aligned.m8n8.x4.shared.b16 {%0,%1,%2,%3}, [%4];"
                 : "=r"(a[0]), "=r"(a[1]), "=r"(a[2]), "=r"(a[3]) : "r"(addr));
}
__device__ __forceinline__ float tanh_a(float x) {
    float r;
    asm("tanh.approx.f32 %0, %1;" : "=f"(r) : "f"(x));
    return r;
}
__device__ __forceinline__ float sig_a(float x) { return fmaf(tanh_a(0.5f * x), 0.5f, 0.5f); }
// k-permutation: unit u -> k' so each thread's owned units are k'-contiguous
__device__ __forceinline__ int sig_k(int u) {
    return 16 * (u >> 4) + 8 * (u & 1) + ((u & 15) >> 1);
}

// ---------------- prep: fragment-packed hi/lo fp16 B image + bias ----------------
__global__ void prep_kernel(const float* __restrict__ Wih, const float* __restrict__ bih,
                            const float* __restrict__ Whh, const float* __restrict__ bhh) {
    int idx = blockIdx.x * blockDim.x + threadIdx.x;
    if (idx < 73728) {
        int kt = idx / 8192, rem = idx - kt * 8192;
        int ntg = rem >> 7, r2 = rem & 127;
        int l = r2 >> 2, s = r2 & 3;
        int p = s >> 1, q = s & 1;
        int n = 8 * ntg + (l >> 2), c = l & 3;
        int row = (n & 3) * 128 + (n >> 2);
        uint32_t pk = 0;
#pragma unroll
        for (int h2 = 0; h2 < 2; h2++) {
            int k = 16 * kt + 2 * c + 8 * q + h2;
            float wv;
            if (k < 128) {
                int a2 = k >> 4, d2 = (k >> 3) & 1, b2 = k & 7;
                wv = Whh[row * 128 + (16 * a2 + 2 * b2 + d2)];
            } else {
                wv = Wih[row * 16 + (k - 128)];
            }
            __half hi = __float2half_rn(wv);
            __half v = p ? __float2half_rn(wv - __half2float(hi)) : hi;
            pk |= (uint32_t)__half_as_ushort(v) << (16 * h2);
        }
        g_B[idx] = pk;
    } else if (idx < 74240) {
        int n = idx - 73728;
        int row = (n & 3) * 128 + (n >> 2);
        g_bias[n] = bih[row] + bhh[row];
    }
}

// ---------------- main kernel ----------------
__global__ __launch_bounds__(NT, 1)
void lstm_mma(const float* __restrict__ rel_in, const float* __restrict__ h0,
              const float* __restrict__ c0, const float* __restrict__ W_sp,
              const float* __restrict__ b_sp, const float* __restrict__ W_out,
              const float* __restrict__ b_out, float* __restrict__ out) {
    extern __shared__ char sm_[];
    char* base = (char*)(((uintptr_t)sm_ + 127) & ~(uintptr_t)127);
    const uint32_t sb = smem_u32(base);
    const int tid = threadIdx.x, w = tid >> 5, l = tid & 31;
    const int g = w >> 3;                      // group 0/1: batch rows [32g, 32g+32)
    const int nc = w & 7;                      // n-cols [64nc, 64nc+64)
    const int tl = tid & 255;
    const int barid = 1 + g;
    const int c = l & 3, quad = l >> 2;
    const int dlt = c >> 1;
    const int row_loc = quad + 8 * (c & 1);
    const int b0 = blockIdx.x * 64;

    float* bias_f = (float*)(base + BIAS_OFF);
    float* wout_f = (float*)(base + WOUT_OFF);
    float* wsp_f  = (float*)(base + WSP_OFF);
    float* bsp_f  = (float*)(base + BSP_OFF);
    float* bout_f = (float*)(base + BOUT_OFF);
    float* relp_f = (float*)(base + RELP_OFF + g * 2048);
    float* rels_f = (float*)(base + RELS_OFF + g * 256);
    volatile int* flag = (volatile int*)(base + FLAG_OFF);

    if (tid < 512) bias_f[tid] = g_bias[tid];
    if (tid < 256) wout_f[tid] = W_out[tid];
    if (tid < 32)  wsp_f[tid]  = W_sp[tid];
    if (tid < 16)  bsp_f[tid]  = b_sp[tid];
    if (tid < 2)   bout_f[tid] = b_out[tid];
    if (tid == 0)  *flag = 0;

    // A init: h0 -> fp16 at permuted k'
    for (int i = tid; i < 8192; i += NT) {
        int m = i >> 7, u = i & 127;
        unsigned short hv = __half_as_ushort(__float2half_rn(h0[(size_t)(b0 + m) * 128 + u]));
        asm volatile("st.shared.u16 [%0], %1;" :: "r"(sb + A_OFF + m * PITCH + sig_k(u) * 2), "h"(hv));
    }
    // x0
    for (int i = tid; i < 1024; i += NT) {
        int m = i >> 4, e = i & 15;
        float r0 = rel_in[(size_t)(b0 + m) * 2], r1 = rel_in[(size_t)(b0 + m) * 2 + 1];
        float xv = tanh_a(fmaf(W_sp[2 * e], r0, fmaf(W_sp[2 * e + 1], r1, b_sp[e])));
        unsigned short hv = __half_as_ushort(__float2half_rn(xv));
        asm volatile("st.shared.u16 [%0], %1;" :: "r"(sb + A_OFF + m * PITCH + (128 + e) * 2), "h"(hv));
    }
    // c state
    float cst[16];
#pragma unroll
    for (int s = 0; s < 2; s++)
#pragma unroll
        for (int j = 0; j < 8; j++)
            cst[s * 8 + j] = c0[(size_t)(b0 + 32 * g + 16 * s + row_loc) * 128 + (16 * nc + 2 * j + dlt)];

    __syncthreads();

    // initial anti-phase skew: group 1 starts half a GEMM later
    if (g == 1) { while (*flag == 0) __nanosleep(200); }

    const uint32_t aAddr0 = sb + A_OFF + (32 * g + (l & 15)) * PITCH + (l >> 4) * 16;
    const int uO = 16 * nc + dlt;
    const uint4* __restrict__ bbase = ((const uint4*)g_B) + (nc * 256 + l);  // +kt*2048 +j*32

    for (int t = 0; t < T_STEPS; t++) {
        float acc[2][8][4];
#pragma unroll
        for (int j = 0; j < 8; j++) {
            float2 bv = *(const float2*)(bias_f + (8 * (nc * 8 + j) + 2 * c));
#pragma unroll
            for (int s = 0; s < 2; s++) {
                acc[s][j][0] = bv.x; acc[s][j][1] = bv.y;
                acc[s][j][2] = bv.x; acc[s][j][3] = bv.y;
            }
        }
        asm volatile("bar.sync %0, 256;" :: "r"(barid) : "memory");  // h/x writes visible

        // ---- free-running GEMM: 72-stage pipeline, B prefetch distance 4 ----
        uint32_t aq[2][2][4];
        ldmatrix4(aq[0][0], aAddr0);
        ldmatrix4(aq[0][1], aAddr0 + 16 * PITCH);
        uint4 bb[4];
#pragma unroll
        for (int i = 0; i < 4; i++)
            bb[i] = bbase[(i >> 3) * 2048 + (i & 7) * 32];
#pragma unroll
        for (int i = 0; i < 72; i++) {
            const int kt = i >> 3, j = i & 7;
            const uint4 b = bb[i & 3];           // READ the operand before the slot is refilled
            if (i + 4 < 72) {
                const int i2 = i + 4;
                bb[i2 & 3] = bbase[(i2 >> 3) * 2048 + (i2 & 7) * 32];
            }
            if (j == 6 && kt < 8) {
                ldmatrix4(aq[(kt + 1) & 1][0], aAddr0 + (kt + 1) * 32);
                ldmatrix4(aq[(kt + 1) & 1][1], aAddr0 + 16 * PITCH + (kt + 1) * 32);
            }
            uint32_t* a0 = aq[kt & 1][0];
            uint32_t* a1 = aq[kt & 1][1];
            mma16816(acc[0][j], a0, b.x, b.y);
            mma16816(acc[0][j], a0, b.z, b.w);
            mma16816(acc[1][j], a1, b.x, b.y);
            mma16816(acc[1][j], a1, b.z, b.w);
            if (i == 36 && t == 0 && g == 0 && tid == 0) *flag = 1;
        }
        asm volatile("bar.sync %0, 256;" :: "r"(barid) : "memory");  // A reads done

        // ---- epilogue ----
        float px[2] = {0.f, 0.f}, py[2] = {0.f, 0.f};
#pragma unroll
        for (int s = 0; s < 2; s++) {
            uint32_t hpk[4];
#pragma unroll
            for (int j = 0; j < 8; j++) {
                float* A4 = acc[s][j];
                float s0 = (c & 1) ? A4[0] : A4[2];
                float s1 = (c & 1) ? A4[1] : A4[3];
                float r0 = __shfl_xor_sync(0xffffffffu, s0, 1);
                float r1 = __shfl_xor_sync(0xffffffffu, s1, 1);
                float zi, zf, zg, zo;
                if ((c & 1) == 0) { zi = A4[0]; zf = A4[1]; zg = r0; zo = r1; }
                else              { zi = r0;    zf = r1;    zg = A4[2]; zo = A4[3]; }
                float cn = sig_a(zf) * cst[s * 8 + j] + sig_a(zi) * tanh_a(zg);
                cst[s * 8 + j] = cn;
                float hv = sig_a(zo) * tanh_a(cn);
                int u = uO + 2 * j;
                px[s] = fmaf(hv, wout_f[u], px[s]);
                py[s] = fmaf(hv, wout_f[128 + u], py[s]);
                uint32_t hb = (uint32_t)__half_as_ushort(__float2half_rn(hv));
                if (j & 1) hpk[j >> 1] |= hb << 16; else hpk[j >> 1] = hb;
            }
            uint32_t ha = sb + A_OFF + (32 * g + 16 * s + row_loc) * PITCH + (16 * nc + 8 * dlt) * 2;
            asm volatile("st.shared.v4.u32 [%0], {%1,%2,%3,%4};"
                         :: "r"(ha), "r"(hpk[0]), "r"(hpk[1]), "r"(hpk[2]), "r"(hpk[3]));
        }
#pragma unroll
        for (int s = 0; s < 2; s++) {
            px[s] += __shfl_xor_sync(0xffffffffu, px[s], 2);
            py[s] += __shfl_xor_sync(0xffffffffu, py[s], 2);
            if (c < 2)
                *(float2*)(relp_f + (nc * 32 + 16 * s + row_loc) * 2) = make_float2(px[s], py[s]);
        }
        asm volatile("bar.sync %0, 256;" :: "r"(barid) : "memory");  // relp visible
        if (tl < 64) {
            int mloc = tl >> 1, cp = tl & 1;
            float r = bout_f[cp];
#pragma unroll
            for (int k = 0; k < 8; k++) r += relp_f[(k * 32 + mloc) * 2 + cp];
            rels_f[mloc * 2 + cp] = r;
            out[(size_t)(b0 + 32 * g + mloc) * (T_STEPS * 2) + t * 2 + cp] = r;
        }
        asm volatile("bar.sync %0, 256;" :: "r"(barid) : "memory");  // rels visible
        for (int i = tl; i < 512; i += 256) {
            int mloc = i >> 4, e = i & 15;
            float xv = tanh_a(fmaf(wsp_f[2 * e], rels_f[mloc * 2],
                              fmaf(wsp_f[2 * e + 1], rels_f[mloc * 2 + 1], bsp_f[e])));
            unsigned short hv = __half_as_ushort(__float2half_rn(xv));
            asm volatile("st.shared.u16 [%0], %1;"
                         :: "r"(sb + A_OFF + (32 * g + mloc) * PITCH + (128 + e) * 2), "h"(hv));
        }
        // next step's first group barrier orders these writes before A reads
    }
}

// ---------------- launch ----------------
extern "C" void kernel_launch(void* const* d_in, const int* in_sizes, int n_in,
                              void* d_out, int out_size) {
    const float* last_obs_rel = (const float*)d_in[1];
    const float* h0    = (const float*)d_in[2];
    const float* c0    = (const float*)d_in[3];
    const float* W_sp  = (const float*)d_in[4];
    const float* b_sp  = (const float*)d_in[5];
    const float* W_ih  = (const float*)d_in[6];
    const float* b_ih  = (const float*)d_in[7];
    const float* W_hh  = (const float*)d_in[8];
    const float* b_hh  = (const float*)d_in[9];
    const float* W_out = (const float*)d_in[10];
    const float* b_out = (const float*)d_in[11];
    float* out = (float*)d_out;

    const int batch = in_sizes[2] / 128;
    const int nblocks = batch / 64;

    cudaFuncSetAttribute(lstm_mma, cudaFuncAttributeMaxDynamicSharedMemorySize, SMEM_REQ);
    prep_kernel<<<146, 512>>>(W_ih, b_ih, W_hh, b_hh);
    lstm_mma<<<nblocks, NT, SMEM_REQ>>>(last_obs_rel, h0, c0, W_sp, b_sp, W_out, b_out, out);
}

// round 16
// speedup vs baseline: 1.0767x; 1.0767x over previous
#include <cuda_runtime.h>
#include <cuda_fp16.h>
#include <cstdint>

#define T_STEPS 30
#define NT 256
#define PITCH 336                 // A row pitch bytes (ldmatrix conflict-free)

// smem byte offsets (per CTA)
#define A_OFF    0                // 32 x 336 = 10752
#define BIAS_OFF 10752            // 512 f32
#define WOUT_OFF 12800            // 256 f32
#define WSP_OFF  13824            // 32 f32
#define BSP_OFF  13952            // 16 f32
#define BOUT_OFF 14016            // 2 f32 (pad 16)
#define RELP_OFF 14032            // 8nc x 32row x 2 f32 = 2048B
#define RELS_OFF 16080            // 32row x 2 f32
#define SMEM_REQ (16336 + 128)

// B image: 9 chunks x [ntg(64)][lane(32)][bh0,bh1,bl0,bl1] (fragment-packed, L2-resident)
__device__ uint32_t g_B[9 * 8192];
__device__ float    g_bias[512];   // indexed by n = 4u+g

__device__ __forceinline__ uint32_t smem_u32(const void* p) {
    uint32_t a;
    asm("{ .reg .u64 t; cvta.to.shared.u64 t, %1; cvt.u32.u64 %0, t; }" : "=r"(a) : "l"(p));
    return a;
}
__device__ __forceinline__ void mma16816(float* d, const uint32_t* a, uint32_t b0, uint32_t b1) {
    asm volatile("mma.sync.aligned.m16n8k16.row.col.f32.f16.f16.f32 "
                 "{%0,%1,%2,%3}, {%4,%5,%6,%7}, {%8,%9}, {%0,%1,%2,%3};"
                 : "+f"(d[0]), "+f"(d[1]), "+f"(d[2]), "+f"(d[3])
                 : "r"(a[0]), "r"(a[1]), "r"(a[2]), "r"(a[3]), "r"(b0), "r"(b1));
}
__device__ __forceinline__ void ldmatrix4(uint32_t* a, uint32_t addr) {
    asm volatile("ldmatrix.sync.aligned.m8n8.x4.shared.b16 {%0,%1,%2,%3}, [%4];"
                 : "=r"(a[0]), "=r"(a[1]), "=r"(a[2]), "=r"(a[3]) : "r"(addr));
}
__device__ __forceinline__ float tanh_a(float x) {
    float r;
    asm("tanh.approx.f32 %0, %1;" : "=f"(r) : "f"(x));
    return r;
}
__device__ __forceinline__ float sig_a(float x) { return fmaf(tanh_a(0.5f * x), 0.5f, 0.5f); }
// k-permutation: unit u -> k' so each thread's owned units are k'-contiguous
__device__ __forceinline__ int sig_k(int u) {
    return 16 * (u >> 4) + 8 * (u & 1) + ((u & 15) >> 1);
}

// ---------------- prep: fragment-packed hi/lo fp16 B image + bias ----------------
__global__ void prep_kernel(const float* __restrict__ Wih, const float* __restrict__ bih,
                            const float* __restrict__ Whh, const float* __restrict__ bhh) {
    int idx = blockIdx.x * blockDim.x + threadIdx.x;
    if (idx < 73728) {
        int kt = idx / 8192, rem = idx - kt * 8192;
        int ntg = rem >> 7, r2 = rem & 127;
        int l = r2 >> 2, s = r2 & 3;
        int p = s >> 1, q = s & 1;
        int n = 8 * ntg + (l >> 2), c = l & 3;
        int row = (n & 3) * 128 + (n >> 2);
        uint32_t pk = 0;
#pragma unroll
        for (int h2 = 0; h2 < 2; h2++) {
            int k = 16 * kt + 2 * c + 8 * q + h2;
            float wv;
            if (k < 128) {
                int a2 = k >> 4, d2 = (k >> 3) & 1, b2 = k & 7;
                wv = Whh[row * 128 + (16 * a2 + 2 * b2 + d2)];
            } else {
                wv = Wih[row * 16 + (k - 128)];
            }
            __half hi = __float2half_rn(wv);
            __half v = p ? __float2half_rn(wv - __half2float(hi)) : hi;
            pk |= (uint32_t)__half_as_ushort(v) << (16 * h2);
        }
        g_B[idx] = pk;
    } else if (idx < 74240) {
        int n = idx - 73728;
        int row = (n & 3) * 128 + (n >> 2);
        g_bias[n] = bih[row] + bhh[row];
    }
}

// ---------------- main kernel: 256-thread CTA, 32 batch rows, 2 CTAs/SM ----------------
__global__ __launch_bounds__(NT, 2)
void lstm_mma(const float* __restrict__ rel_in, const float* __restrict__ h0,
              const float* __restrict__ c0, const float* __restrict__ W_sp,
              const float* __restrict__ b_sp, const float* __restrict__ W_out,
              const float* __restrict__ b_out, float* __restrict__ out) {
    extern __shared__ char sm_[];
    char* base = (char*)(((uintptr_t)sm_ + 127) & ~(uintptr_t)127);
    const uint32_t sb = smem_u32(base);
    const int tid = threadIdx.x, w = tid >> 5, l = tid & 31;
    const int nc = w;                          // 8 warps: n-cols [64nc, 64nc+64)
    const int c = l & 3, quad = l >> 2;
    const int dlt = c >> 1;
    const int row_loc = quad + 8 * (c & 1);
    const int b0 = blockIdx.x * 32;

    float* bias_f = (float*)(base + BIAS_OFF);
    float* wout_f = (float*)(base + WOUT_OFF);
    float* wsp_f  = (float*)(base + WSP_OFF);
    float* bsp_f  = (float*)(base + BSP_OFF);
    float* bout_f = (float*)(base + BOUT_OFF);
    float* relp_f = (float*)(base + RELP_OFF);
    float* rels_f = (float*)(base + RELS_OFF);

    for (int i = tid; i < 512; i += NT) bias_f[i] = g_bias[i];
    if (tid < 256) wout_f[tid] = W_out[tid];
    if (tid < 32)  wsp_f[tid]  = W_sp[tid];
    if (tid < 16)  bsp_f[tid]  = b_sp[tid];
    if (tid < 2)   bout_f[tid] = b_out[tid];

    // A init: h0 -> fp16 at permuted k' (32 rows)
    for (int i = tid; i < 4096; i += NT) {
        int m = i >> 7, u = i & 127;
        unsigned short hv = __half_as_ushort(__float2half_rn(h0[(size_t)(b0 + m) * 128 + u]));
        asm volatile("st.shared.u16 [%0], %1;" :: "r"(sb + A_OFF + m * PITCH + sig_k(u) * 2), "h"(hv));
    }
    // x0
    for (int i = tid; i < 512; i += NT) {
        int m = i >> 4, e = i & 15;
        float r0 = rel_in[(size_t)(b0 + m) * 2], r1 = rel_in[(size_t)(b0 + m) * 2 + 1];
        float xv = tanh_a(fmaf(W_sp[2 * e], r0, fmaf(W_sp[2 * e + 1], r1, b_sp[e])));
        unsigned short hv = __half_as_ushort(__float2half_rn(xv));
        asm volatile("st.shared.u16 [%0], %1;" :: "r"(sb + A_OFF + m * PITCH + (128 + e) * 2), "h"(hv));
    }
    // c state: thread owns rows 16s+row_loc (s=0,1), units 16nc+2j+dlt (j=0..7)
    float cst[16];
#pragma unroll
    for (int s = 0; s < 2; s++)
#pragma unroll
        for (int j = 0; j < 8; j++)
            cst[s * 8 + j] = c0[(size_t)(b0 + 16 * s + row_loc) * 128 + (16 * nc + 2 * j + dlt)];

    __syncthreads();

    const uint32_t aAddr0 = sb + A_OFF + (l & 15) * PITCH + (l >> 4) * 16;
    const int uO = 16 * nc + dlt;
    const uint4* __restrict__ bbase = ((const uint4*)g_B) + (nc * 256 + l);  // +kt*2048 +j*32

    for (int t = 0; t < T_STEPS; t++) {
        float acc[2][8][4];
#pragma unroll
        for (int j = 0; j < 8; j++) {
            float2 bv = *(const float2*)(bias_f + (8 * (nc * 8 + j) + 2 * c));
#pragma unroll
            for (int s = 0; s < 2; s++) {
                acc[s][j][0] = bv.x; acc[s][j][1] = bv.y;
                acc[s][j][2] = bv.x; acc[s][j][3] = bv.y;
            }
        }
        __syncthreads();   // h/x writes visible

        // ---- free-running GEMM: 72-stage pipeline, ring 3, prefetch distance 2 ----
        uint32_t aq[2][2][4];
        ldmatrix4(aq[0][0], aAddr0);
        ldmatrix4(aq[0][1], aAddr0 + 16 * PITCH);
        uint4 bb[3];
        bb[0] = bbase[0];
        bb[1] = bbase[32];
#pragma unroll
        for (int i = 0; i < 72; i++) {
            const int kt = i >> 3, j = i & 7;
            if (i + 2 < 72) {
                const int i2 = i + 2;
                bb[i2 % 3] = bbase[(i2 >> 3) * 2048 + (i2 & 7) * 32];
            }
            if (j == 6 && kt < 8) {
                ldmatrix4(aq[(kt + 1) & 1][0], aAddr0 + (kt + 1) * 32);
                ldmatrix4(aq[(kt + 1) & 1][1], aAddr0 + 16 * PITCH + (kt + 1) * 32);
            }
            const uint4 b = bb[i % 3];
            uint32_t* a0 = aq[kt & 1][0];
            uint32_t* a1 = aq[kt & 1][1];
            mma16816(acc[0][j], a0, b.x, b.y);
            mma16816(acc[0][j], a0, b.z, b.w);
            mma16816(acc[1][j], a1, b.x, b.y);
            mma16816(acc[1][j], a1, b.z, b.w);
        }
        __syncthreads();   // A reads done before h overwrite

        // ---- epilogue ----
        float px[2] = {0.f, 0.f}, py[2] = {0.f, 0.f};
#pragma unroll
        for (int s = 0; s < 2; s++) {
            uint32_t hpk[4];
#pragma unroll
            for (int j = 0; j < 8; j++) {
                float* A4 = acc[s][j];
                float s0 = (c & 1) ? A4[0] : A4[2];
                float s1 = (c & 1) ? A4[1] : A4[3];
                float r0 = __shfl_xor_sync(0xffffffffu, s0, 1);
                float r1 = __shfl_xor_sync(0xffffffffu, s1, 1);
                float zi, zf, zg, zo;
                if ((c & 1) == 0) { zi = A4[0]; zf = A4[1]; zg = r0; zo = r1; }
                else              { zi = r0;    zf = r1;    zg = A4[2]; zo = A4[3]; }
                float cn = sig_a(zf) * cst[s * 8 + j] + sig_a(zi) * tanh_a(zg);
                cst[s * 8 + j] = cn;
                float hv = sig_a(zo) * tanh_a(cn);
                int u = uO + 2 * j;
                px[s] = fmaf(hv, wout_f[u], px[s]);
                py[s] = fmaf(hv, wout_f[128 + u], py[s]);
                uint32_t hb = (uint32_t)__half_as_ushort(__float2half_rn(hv));
                if (j & 1) hpk[j >> 1] |= hb << 16; else hpk[j >> 1] = hb;
            }
            uint32_t ha = sb + A_OFF + (16 * s + row_loc) * PITCH + (16 * nc + 8 * dlt) * 2;
            asm volatile("st.shared.v4.u32 [%0], {%1,%2,%3,%4};"
                         :: "r"(ha), "r"(hpk[0]), "r"(hpk[1]), "r"(hpk[2]), "r"(hpk[3]));
        }
#pragma unroll
        for (int s = 0; s < 2; s++) {
            px[s] += __shfl_xor_sync(0xffffffffu, px[s], 2);
            py[s] += __shfl_xor_sync(0xffffffffu, py[s], 2);
            if (c < 2)
                *(float2*)(relp_f + (nc * 32 + 16 * s + row_loc) * 2) = make_float2(px[s], py[s]);
        }
        __syncthreads();   // relp visible
        if (tid < 64) {
            int mloc = tid >> 1, cp = tid & 1;
            float r = bout_f[cp];
#pragma unroll
            for (int k = 0; k < 8; k++) r += relp_f[(k * 32 + mloc) * 2 + cp];
            rels_f[mloc * 2 + cp] = r;
            out[(size_t)(b0 + mloc) * (T_STEPS * 2) + t * 2 + cp] = r;
        }
        __syncthreads();   // rels visible
        for (int i = tid; i < 512; i += NT) {
            int mloc = i >> 4, e = i & 15;
            float xv = tanh_a(fmaf(wsp_f[2 * e], rels_f[mloc * 2],
                              fmaf(wsp_f[2 * e + 1], rels_f[mloc * 2 + 1], bsp_f[e])));
            unsigned short hv = __half_as_ushort(__float2half_rn(xv));
            asm volatile("st.shared.u16 [%0], %1;"
                         :: "r"(sb + A_OFF + mloc * PITCH + (128 + e) * 2), "h"(hv));
        }
        // next step's first __syncthreads orders these writes before A reads
    }
}

// ---------------- launch ----------------
extern "C" void kernel_launch(void* const* d_in, const int* in_sizes, int n_in,
                              void* d_out, int out_size) {
    const float* last_obs_rel = (const float*)d_in[1];
    const float* h0    = (const float*)d_in[2];
    const float* c0    = (const float*)d_in[3];
    const float* W_sp  = (const float*)d_in[4];
    const float* b_sp  = (const float*)d_in[5];
    const float* W_ih  = (const float*)d_in[6];
    const float* b_ih  = (const float*)d_in[7];
    const float* W_hh  = (const float*)d_in[8];
    const float* b_hh  = (const float*)d_in[9];
    const float* W_out = (const float*)d_in[10];
    const float* b_out = (const float*)d_in[11];
    float* out = (float*)d_out;

    const int batch = in_sizes[2] / 128;
    const int nblocks = batch / 32;

    cudaFuncSetAttribute(lstm_mma, cudaFuncAttributeMaxDynamicSharedMemorySize, SMEM_REQ);
    prep_kernel<<<146, 512>>>(W_ih, b_ih, W_hh, b_hh);
    lstm_mma<<<nblocks, NT, SMEM_REQ>>>(last_obs_rel, h0, c0, W_sp, b_sp, W_out, b_out, out);
}

// round 17
// speedup vs baseline: 1.6458x; 1.5286x over previous
#include <cuda_runtime.h>
#include <cuda_fp16.h>
#include <cstdint>

#define T_STEPS 30
#define NT 256
#define PITCH 336                 // A row pitch bytes (ldmatrix conflict-free)

// smem byte offsets (per CTA)
#define A_OFF    0                // 32 x 336 = 10752
#define BIAS_OFF 10752            // 512 f32
#define WOUT_OFF 12800            // 256 f32
#define WSP_OFF  13824            // 32 f32
#define BSP_OFF  13952            // 16 f32
#define BOUT_OFF 14016            // 2 f32 (pad 16)
#define RELP_OFF 14032            // 8nc x 32row x 2 f32 = 2048B
#define RELS_OFF 16080            // 32row x 2 f32
#define SMEM_REQ (16336 + 128)

// B image (single fp16 plane): 9 chunks x [ntg(64)][lane(32)][q(2)] u32, fragment-packed
__device__ uint32_t g_B[9 * 4096];
__device__ float    g_bias[512];   // indexed by n = 4u+g

__device__ __forceinline__ uint32_t smem_u32(const void* p) {
    uint32_t a;
    asm("{ .reg .u64 t; cvta.to.shared.u64 t, %1; cvt.u32.u64 %0, t; }" : "=r"(a) : "l"(p));
    return a;
}
__device__ __forceinline__ void mma16816(float* d, const uint32_t* a, uint32_t b0, uint32_t b1) {
    asm volatile("mma.sync.aligned.m16n8k16.row.col.f32.f16.f16.f32 "
                 "{%0,%1,%2,%3}, {%4,%5,%6,%7}, {%8,%9}, {%0,%1,%2,%3};"
                 : "+f"(d[0]), "+f"(d[1]), "+f"(d[2]), "+f"(d[3])
                 : "r"(a[0]), "r"(a[1]), "r"(a[2]), "r"(a[3]), "r"(b0), "r"(b1));
}
__device__ __forceinline__ void ldmatrix4(uint32_t* a, uint32_t addr) {
    asm volatile("ldmatrix.sync.aligned.m8n8.x4.shared.b16 {%0,%1,%2,%3}, [%4];"
                 : "=r"(a[0]), "=r"(a[1]), "=r"(a[2]), "=r"(a[3]) : "r"(addr));
}
__device__ __forceinline__ float tanh_a(float x) {
    float r;
    asm("tanh.approx.f32 %0, %1;" : "=f"(r) : "f"(x));
    return r;
}
__device__ __forceinline__ float sig_a(float x) { return fmaf(tanh_a(0.5f * x), 0.5f, 0.5f); }
// k-permutation: unit u -> k' so each thread's owned units are k'-contiguous
__device__ __forceinline__ int sig_k(int u) {
    return 16 * (u >> 4) + 8 * (u & 1) + ((u & 15) >> 1);
}

// ---------------- prep: fragment-packed fp16 B image + bias ----------------
__global__ void prep_kernel(const float* __restrict__ Wih, const float* __restrict__ bih,
                            const float* __restrict__ Whh, const float* __restrict__ bhh) {
    int idx = blockIdx.x * blockDim.x + threadIdx.x;
    if (idx < 36864) {
        int kt = idx / 4096, rem = idx - kt * 4096;
        int ntg = rem >> 6, r2 = rem & 63;
        int l = r2 >> 1, q = r2 & 1;
        int n = 8 * ntg + (l >> 2), c = l & 3;
        int row = (n & 3) * 128 + (n >> 2);     // torch row for gate (n&3), unit (n>>2)
        uint32_t pk = 0;
#pragma unroll
        for (int h2 = 0; h2 < 2; h2++) {
            int k = 16 * kt + 2 * c + 8 * q + h2;
            float wv;
            if (k < 128) {
                int a2 = k >> 4, d2 = (k >> 3) & 1, b2 = k & 7;
                wv = Whh[row * 128 + (16 * a2 + 2 * b2 + d2)];   // inverse sig_k
            } else {
                wv = Wih[row * 16 + (k - 128)];
            }
            pk |= (uint32_t)__half_as_ushort(__float2half_rn(wv)) << (16 * h2);
        }
        g_B[idx] = pk;
    } else if (idx < 37376) {
        int n = idx - 36864;
        int row = (n & 3) * 128 + (n >> 2);
        g_bias[n] = bih[row] + bhh[row];
    }
}

// ---------------- main kernel: 256-thread CTA, 32 batch rows, 2 CTAs/SM ----------------
__global__ __launch_bounds__(NT, 2)
void lstm_mma(const float* __restrict__ rel_in, const float* __restrict__ h0,
              const float* __restrict__ c0, const float* __restrict__ W_sp,
              const float* __restrict__ b_sp, const float* __restrict__ W_out,
              const float* __restrict__ b_out, float* __restrict__ out) {
    extern __shared__ char sm_[];
    char* base = (char*)(((uintptr_t)sm_ + 127) & ~(uintptr_t)127);
    const uint32_t sb = smem_u32(base);
    const int tid = threadIdx.x, w = tid >> 5, l = tid & 31;
    const int nc = w;                          // 8 warps: n-cols [64nc, 64nc+64)
    const int c = l & 3, quad = l >> 2;
    const int dlt = c >> 1;
    const int row_loc = quad + 8 * (c & 1);
    const int b0 = blockIdx.x * 32;

    float* bias_f = (float*)(base + BIAS_OFF);
    float* wout_f = (float*)(base + WOUT_OFF);
    float* wsp_f  = (float*)(base + WSP_OFF);
    float* bsp_f  = (float*)(base + BSP_OFF);
    float* bout_f = (float*)(base + BOUT_OFF);
    float* relp_f = (float*)(base + RELP_OFF);
    float* rels_f = (float*)(base + RELS_OFF);

    for (int i = tid; i < 512; i += NT) bias_f[i] = g_bias[i];
    if (tid < 256) wout_f[tid] = W_out[tid];
    if (tid < 32)  wsp_f[tid]  = W_sp[tid];
    if (tid < 16)  bsp_f[tid]  = b_sp[tid];
    if (tid < 2)   bout_f[tid] = b_out[tid];

    // A init: h0 -> fp16 at permuted k' (32 rows)
    for (int i = tid; i < 4096; i += NT) {
        int m = i >> 7, u = i & 127;
        unsigned short hv = __half_as_ushort(__float2half_rn(h0[(size_t)(b0 + m) * 128 + u]));
        asm volatile("st.shared.u16 [%0], %1;" :: "r"(sb + A_OFF + m * PITCH + sig_k(u) * 2), "h"(hv));
    }
    // x0
    for (int i = tid; i < 512; i += NT) {
        int m = i >> 4, e = i & 15;
        float r0 = rel_in[(size_t)(b0 + m) * 2], r1 = rel_in[(size_t)(b0 + m) * 2 + 1];
        float xv = tanh_a(fmaf(W_sp[2 * e], r0, fmaf(W_sp[2 * e + 1], r1, b_sp[e])));
        unsigned short hv = __half_as_ushort(__float2half_rn(xv));
        asm volatile("st.shared.u16 [%0], %1;" :: "r"(sb + A_OFF + m * PITCH + (128 + e) * 2), "h"(hv));
    }
    // c state: thread owns rows 16s+row_loc (s=0,1), units 16nc+2j+dlt (j=0..7)
    float cst[16];
#pragma unroll
    for (int s = 0; s < 2; s++)
#pragma unroll
        for (int j = 0; j < 8; j++)
            cst[s * 8 + j] = c0[(size_t)(b0 + 16 * s + row_loc) * 128 + (16 * nc + 2 * j + dlt)];

    __syncthreads();

    const uint32_t aAddr0 = sb + A_OFF + (l & 15) * PITCH + (l >> 4) * 16;
    const int uO = 16 * nc + dlt;
    const uint2* __restrict__ bbase = ((const uint2*)g_B) + (nc * 256 + l);  // +kt*2048 +j*32

    for (int t = 0; t < T_STEPS; t++) {
        float acc[2][8][4];
#pragma unroll
        for (int j = 0; j < 8; j++) {
            float2 bv = *(const float2*)(bias_f + (8 * (nc * 8 + j) + 2 * c));
#pragma unroll
            for (int s = 0; s < 2; s++) {
                acc[s][j][0] = bv.x; acc[s][j][1] = bv.y;
                acc[s][j][2] = bv.x; acc[s][j][3] = bv.y;
            }
        }
        __syncthreads();   // h/x writes visible

        // ---- free-running GEMM: 72-stage pipeline, ring 3, prefetch distance 2 ----
        uint32_t aq[2][2][4];
        ldmatrix4(aq[0][0], aAddr0);
        ldmatrix4(aq[0][1], aAddr0 + 16 * PITCH);
        uint2 bb[3];
        bb[0] = bbase[0];
        bb[1] = bbase[32];
#pragma unroll
        for (int i = 0; i < 72; i++) {
            const int kt = i >> 3, j = i & 7;
            if (i + 2 < 72) {
                const int i2 = i + 2;
                bb[i2 % 3] = bbase[(i2 >> 3) * 2048 + (i2 & 7) * 32];
            }
            if (j == 6 && kt < 8) {
                ldmatrix4(aq[(kt + 1) & 1][0], aAddr0 + (kt + 1) * 32);
                ldmatrix4(aq[(kt + 1) & 1][1], aAddr0 + 16 * PITCH + (kt + 1) * 32);
            }
            const uint2 b = bb[i % 3];
            mma16816(acc[0][j], aq[kt & 1][0], b.x, b.y);
            mma16816(acc[1][j], aq[kt & 1][1], b.x, b.y);
        }
        __syncthreads();   // A reads done before h overwrite

        // ---- epilogue ----
        float px[2] = {0.f, 0.f}, py[2] = {0.f, 0.f};
#pragma unroll
        for (int s = 0; s < 2; s++) {
            uint32_t hpk[4];
#pragma unroll
            for (int j = 0; j < 8; j++) {
                float* A4 = acc[s][j];
                float s0 = (c & 1) ? A4[0] : A4[2];
                float s1 = (c & 1) ? A4[1] : A4[3];
                float r0 = __shfl_xor_sync(0xffffffffu, s0, 1);
                float r1 = __shfl_xor_sync(0xffffffffu, s1, 1);
                float zi, zf, zg, zo;
                if ((c & 1) == 0) { zi = A4[0]; zf = A4[1]; zg = r0; zo = r1; }
                else              { zi = r0;    zf = r1;    zg = A4[2]; zo = A4[3]; }
                float cn = sig_a(zf) * cst[s * 8 + j] + sig_a(zi) * tanh_a(zg);
                cst[s * 8 + j] = cn;
                float hv = sig_a(zo) * tanh_a(cn);
                int u = uO + 2 * j;
                px[s] = fmaf(hv, wout_f[u], px[s]);
                py[s] = fmaf(hv, wout_f[128 + u], py[s]);
                uint32_t hb = (uint32_t)__half_as_ushort(__float2half_rn(hv));
                if (j & 1) hpk[j >> 1] |= hb << 16; else hpk[j >> 1] = hb;
            }
            uint32_t ha = sb + A_OFF + (16 * s + row_loc) * PITCH + (16 * nc + 8 * dlt) * 2;
            asm volatile("st.shared.v4.u32 [%0], {%1,%2,%3,%4};"
                         :: "r"(ha), "r"(hpk[0]), "r"(hpk[1]), "r"(hpk[2]), "r"(hpk[3]));
        }
#pragma unroll
        for (int s = 0; s < 2; s++) {
            px[s] += __shfl_xor_sync(0xffffffffu, px[s], 2);
            py[s] += __shfl_xor_sync(0xffffffffu, py[s], 2);
            if (c < 2)
                *(float2*)(relp_f + (nc * 32 + 16 * s + row_loc) * 2) = make_float2(px[s], py[s]);
        }
        __syncthreads();   // relp visible
        if (tid < 64) {
            int mloc = tid >> 1, cp = tid & 1;
            float r = bout_f[cp];
#pragma unroll
            for (int k = 0; k < 8; k++) r += relp_f[(k * 32 + mloc) * 2 + cp];
            rels_f[mloc * 2 + cp] = r;
            out[(size_t)(b0 + mloc) * (T_STEPS * 2) + t * 2 + cp] = r;
        }
        __syncthreads();   // rels visible
        for (int i = tid; i < 512; i += NT) {
            int mloc = i >> 4, e = i & 15;
            float xv = tanh_a(fmaf(wsp_f[2 * e], rels_f[mloc * 2],
                              fmaf(wsp_f[2 * e + 1], rels_f[mloc * 2 + 1], bsp_f[e])));
            unsigned short hv = __half_as_ushort(__float2half_rn(xv));
            asm volatile("st.shared.u16 [%0], %1;"
                         :: "r"(sb + A_OFF + mloc * PITCH + (128 + e) * 2), "h"(hv));
        }
        // next step's first __syncthreads orders these writes before A reads
    }
}

// ---------------- launch ----------------
extern "C" void kernel_launch(void* const* d_in, const int* in_sizes, int n_in,
                              void* d_out, int out_size) {
    const float* last_obs_rel = (const float*)d_in[1];
    const float* h0    = (const float*)d_in[2];
    const float* c0    = (const float*)d_in[3];
    const float* W_sp  = (const float*)d_in[4];
    const float* b_sp  = (const float*)d_in[5];
    const float* W_ih  = (const float*)d_in[6];
    const float* b_ih  = (const float*)d_in[7];
    const float* W_hh  = (const float*)d_in[8];
    const float* b_hh  = (const float*)d_in[9];
    const float* W_out = (const float*)d_in[10];
    const float* b_out = (const float*)d_in[11];
    float* out = (float*)d_out;

    const int batch = in_sizes[2] / 128;
    const int nblocks = batch / 32;

    cudaFuncSetAttribute(lstm_mma, cudaFuncAttributeMaxDynamicSharedMemorySize, SMEM_REQ);
    prep_kernel<<<73, 512>>>(W_ih, b_ih, W_hh, b_hh);
    lstm_mma<<<nblocks, NT, SMEM_REQ>>>(last_obs_rel, h0, c0, W_sp, b_sp, W_out, b_out, out);
}